// round 11
// baseline (speedup 1.0000x reference)
#include <cuda_runtime.h>
#include <math.h>

#define Bb   8
#define Hh   32
#define Ss   4096
#define HD   128
#define Dd   4096
#define KV   4097          // Ss + 1 new token
#define SSTR 4112          // padded score stride
#define CAND 3585          // KV - RECENT(512)
#define KEEP 516           // IMP_SIZE(4) + RECENT(512)
#define KC   64            // split-K chunk for projections
#define NPART 64           // split-K partials per (b,h): 8 chunks x 8 warps

#define OFF_K   32768
#define OFF_V   (32768 + 16908288)
#define OFF_IMP (32768 + 2*16908288)

// ---------------- static scratch (no allocations allowed) ----------------
__device__ float g_q[Bb*Dd];
__device__ float g_k[Bb*Dd];
__device__ float g_v[Bb*Dd];
__device__ float g_scores[Bb*Hh*SSTR];
__device__ float g_m[Bb*Hh];
__device__ float g_il[Bb*Hh];        // 1/l
__device__ float g_ctx[Bb*Hh*HD];    // == Bb*Dd floats
__device__ float g_imp[Bb*KV];
__device__ int   g_topk[Bb*4];
__device__ float g_pm[Bb*Hh*NPART];
__device__ float g_pl[Bb*Hh*NPART];
__device__ float g_pctx[Bb*Hh*NPART*HD];   // 8 MB partial ctx
__device__ float g_cos[64];
__device__ float g_sin[64];

__device__ __forceinline__ bool better(float v1, int i1, float v2, int i2) {
    return (v1 > v2) || (v1 == v2 && i1 < i2);
}
__device__ __forceinline__ void ins4(float v, int i, float* bv, int* bi) {
    #pragma unroll
    for (int r=0;r<4;r++) {
        if (better(v, i, bv[r], bi[r])) {
            #pragma unroll
            for (int q=3;q>r;q--){ bv[q]=bv[q-1]; bi[q]=bi[q-1]; }
            bv[r]=v; bi[r]=i; return;
        }
    }
}

// shared GEMV body: accumulate into dst (a __device__ global, referenced in device code)
__device__ __forceinline__ void proj_body(const float* __restrict__ hs,
                                          const float* __restrict__ W,
                                          float* dst, int i0, int j,
                                          float* h_sm) {
    for (int idx = threadIdx.x; idx < Bb*KC; idx += blockDim.x)
        h_sm[idx] = hs[(idx/KC)*Dd + i0 + (idx%KC)];
    __syncthreads();

    float4 acc[Bb];
    #pragma unroll
    for (int b=0;b<Bb;b++) acc[b] = make_float4(0.f,0.f,0.f,0.f);

    const float4* Wp = (const float4*)(W + (size_t)i0*Dd + j);
    for (int ii=0; ii<KC; ii+=4) {
        float4 w0 = __ldcs(&Wp[(size_t)(ii+0)*(Dd/4)]);
        float4 w1 = __ldcs(&Wp[(size_t)(ii+1)*(Dd/4)]);
        float4 w2 = __ldcs(&Wp[(size_t)(ii+2)*(Dd/4)]);
        float4 w3 = __ldcs(&Wp[(size_t)(ii+3)*(Dd/4)]);
        #pragma unroll
        for (int b=0;b<Bb;b++) {
            float h0 = h_sm[b*KC+ii+0], h1 = h_sm[b*KC+ii+1];
            float h2 = h_sm[b*KC+ii+2], h3 = h_sm[b*KC+ii+3];
            acc[b].x += h0*w0.x + h1*w1.x + h2*w2.x + h3*w3.x;
            acc[b].y += h0*w0.y + h1*w1.y + h2*w2.y + h3*w3.y;
            acc[b].z += h0*w0.z + h1*w1.z + h2*w2.z + h3*w3.z;
            acc[b].w += h0*w0.w + h1*w1.w + h2*w2.w + h3*w3.w;
        }
    }
    #pragma unroll
    for (int b=0;b<Bb;b++) {
        atomicAdd(&dst[b*Dd+j  ], acc[b].x);
        atomicAdd(&dst[b*Dd+j+1], acc[b].y);
        atomicAdd(&dst[b*Dd+j+2], acc[b].z);
        atomicAdd(&dst[b*Dd+j+3], acc[b].w);
    }
}

// ---------------- 1. zero accumulators + rope table ----------------
__global__ void k_zero(float* out0) {
    int i = blockIdx.x*blockDim.x + threadIdx.x;
    if (i < Bb*Dd) { g_q[i]=0.f; g_k[i]=0.f; g_v[i]=0.f; out0[i]=0.f; }
    if (blockIdx.x == 0 && threadIdx.x < 64) {
        double ang = 4096.0 * pow(10000.0, -(double)(2*threadIdx.x)/128.0);
        g_cos[threadIdx.x] = (float)cos(ang);
        g_sin[threadIdx.x] = (float)sin(ang);
    }
}

// ---------------- 2a. Q projection (writes g_q internally) ----------------
__global__ void k_projQ(const float* __restrict__ hs, const float* __restrict__ Wq) {
    __shared__ float h_sm[Bb*KC];
    proj_body(hs, Wq, g_q, blockIdx.y*KC, blockIdx.x*512 + threadIdx.x*4, h_sm);
}

// ---------------- 2b. K+V projection (z=0 -> g_k, z=1 -> g_v) ----------------
__global__ void k_projKV(const float* __restrict__ hs,
                         const float* __restrict__ Wk,
                         const float* __restrict__ Wv) {
    __shared__ float h_sm[Bb*KC];
    const float* W = (blockIdx.z==0) ? Wk : Wv;
    float* dst     = (blockIdx.z==0) ? g_k : g_v;
    proj_body(hs, W, dst, blockIdx.y*KC, blockIdx.x*512 + threadIdx.x*4, h_sm);
}

// ---------------- 3. fused scores + online-softmax ctx + recent evict (q roped inline) ----
// grid (8, Bb*Hh), 256 threads (8 warps). warp handles 64 contiguous tokens.
__global__ void k_fused(const float* __restrict__ Kc, const float* __restrict__ Vc,
                        float* __restrict__ out) {
    int bh   = blockIdx.y;
    int warp = threadIdx.x >> 5, lane = threadIdx.x & 31;
    int s0   = blockIdx.x*512 + warp*64;
    float4 q4 = ((const float4*)(g_q + (bh/Hh)*Dd + (bh%Hh)*HD))[lane];
    // inline RoPE on q: partner lane is lane^16 (dims +-64)
    {
        float4 p4;
        p4.x = __shfl_xor_sync(0xFFFFFFFFu, q4.x, 16);
        p4.y = __shfl_xor_sync(0xFFFFFFFFu, q4.y, 16);
        p4.z = __shfl_xor_sync(0xFFFFFFFFu, q4.z, 16);
        p4.w = __shfl_xor_sync(0xFFFFFFFFu, q4.w, 16);
        float sign = (lane < 16) ? -1.f : 1.f;
        int i0 = (4*lane) & 63;
        float c0=g_cos[i0],   s0r=g_sin[i0];
        float c1=g_cos[i0+1], s1=g_sin[i0+1];
        float c2=g_cos[i0+2], s2=g_sin[i0+2];
        float c3=g_cos[i0+3], s3=g_sin[i0+3];
        q4.x = q4.x*c0 + sign*p4.x*s0r;
        q4.y = q4.y*c1 + sign*p4.y*s1;
        q4.z = q4.z*c2 + sign*p4.z*s2;
        q4.w = q4.w*c3 + sign*p4.w*s3;
    }
    const float4* Kp = (const float4*)Kc + (size_t)bh*Ss*32;
    const float4* Vp = (const float4*)Vc + (size_t)bh*Ss*32;
    float4* outK = (float4*)(out + OFF_K) + (size_t)bh*KEEP*32 + lane;
    float4* outV = (float4*)(out + OFF_V) + (size_t)bh*KEEP*32 + lane;
    float* sc = g_scores + (size_t)bh*SSTR;
    const float scale = 0.08838834764831845f;

    float m = -1e30f, l = 0.f;
    float4 acc = make_float4(0.f,0.f,0.f,0.f);

    for (int s = s0; s < s0+64; s += 4) {
        float4 k0 = Kp[(size_t)(s+0)*32 + lane];
        float4 k1 = Kp[(size_t)(s+1)*32 + lane];
        float4 k2 = Kp[(size_t)(s+2)*32 + lane];
        float4 k3 = Kp[(size_t)(s+3)*32 + lane];
        float4 v0 = Vp[(size_t)(s+0)*32 + lane];
        float4 v1 = Vp[(size_t)(s+1)*32 + lane];
        float4 v2 = Vp[(size_t)(s+2)*32 + lane];
        float4 v3 = Vp[(size_t)(s+3)*32 + lane];
        float d0 = q4.x*k0.x + q4.y*k0.y + q4.z*k0.z + q4.w*k0.w;
        float d1 = q4.x*k1.x + q4.y*k1.y + q4.z*k1.z + q4.w*k1.w;
        float d2 = q4.x*k2.x + q4.y*k2.y + q4.z*k2.z + q4.w*k2.w;
        float d3 = q4.x*k3.x + q4.y*k3.y + q4.z*k3.z + q4.w*k3.w;
        #pragma unroll
        for (int off=16; off; off>>=1) {
            d0 += __shfl_xor_sync(0xFFFFFFFFu, d0, off);
            d1 += __shfl_xor_sync(0xFFFFFFFFu, d1, off);
            d2 += __shfl_xor_sync(0xFFFFFFFFu, d2, off);
            d3 += __shfl_xor_sync(0xFFFFFFFFu, d3, off);
        }
        d0 *= scale; d1 *= scale; d2 *= scale; d3 *= scale;
        if (lane == 0) { sc[s]=d0; sc[s+1]=d1; sc[s+2]=d2; sc[s+3]=d3; }
        // recent-window eviction copy: tokens [CAND, Ss) -> keep slot 4 + (tok-CAND)
        if (s+3 >= CAND) {
            if (s+0 >= CAND) { outK[(size_t)(s+0-CAND+4)*32]=k0; outV[(size_t)(s+0-CAND+4)*32]=v0; }
            if (s+1 >= CAND) { outK[(size_t)(s+1-CAND+4)*32]=k1; outV[(size_t)(s+1-CAND+4)*32]=v1; }
            { outK[(size_t)(s+2-CAND+4)*32]=k2; outV[(size_t)(s+2-CAND+4)*32]=v2; }
            { outK[(size_t)(s+3-CAND+4)*32]=k3; outV[(size_t)(s+3-CAND+4)*32]=v3; }
        }
        float gm = fmaxf(m, fmaxf(fmaxf(d0,d1), fmaxf(d2,d3)));
        float r  = expf(m - gm);
        float p0 = expf(d0-gm), p1 = expf(d1-gm);
        float p2 = expf(d2-gm), p3 = expf(d3-gm);
        l = l*r + (p0+p1) + (p2+p3);
        acc.x = acc.x*r + p0*v0.x + p1*v1.x + p2*v2.x + p3*v3.x;
        acc.y = acc.y*r + p0*v0.y + p1*v1.y + p2*v2.y + p3*v3.y;
        acc.z = acc.z*r + p0*v0.z + p1*v1.z + p2*v2.z + p3*v3.z;
        acc.w = acc.w*r + p0*v0.w + p1*v1.w + p2*v2.w + p3*v3.w;
        m = gm;
    }
    int pid = bh*NPART + blockIdx.x*8 + warp;
    if (lane == 0) { g_pm[pid] = m; g_pl[pid] = l; }
    ((float4*)g_pctx)[(size_t)pid*32 + lane] = acc;
}

// ---------------- 4. combine: rope q/k, new-token score, merge partials, evict slot 515 ----
__global__ void k_comb(float* __restrict__ out) {
    int bh = blockIdx.x;
    int d  = threadIdx.x;                  // 128 threads
    __shared__ float sq[HD], sk[HD], red[HD];
    __shared__ float sm_m[NPART], sm_l[NPART], sm_w[NPART];
    int base = (bh/Hh)*Dd + (bh%Hh)*HD;
    sq[d] = g_q[base+d]; sk[d] = g_k[base+d];
    if (d < NPART) { sm_m[d] = g_pm[bh*NPART+d]; sm_l[d] = g_pl[bh*NPART+d]; }
    __syncthreads();
    int i = d & 63;
    float c = g_cos[i], s = g_sin[i];
    float qr = (d<64) ? -sq[d+64] : sq[d-64];
    float kr = (d<64) ? -sk[d+64] : sk[d-64];
    float qn = sq[d]*c + qr*s;
    float kn = sk[d]*c + kr*s;
    red[d] = qn*kn;
    __syncthreads();
    for (int st=64; st>0; st>>=1) { if (d<st) red[d]+=red[d+st]; __syncthreads(); }
    float sNew = red[0] * 0.08838834764831845f;
    if (d == 0) g_scores[(size_t)bh*SSTR + Ss] = sNew;

    float M = sNew;
    #pragma unroll 8
    for (int i2=0;i2<NPART;i2++) M = fmaxf(M, sm_m[i2]);
    __syncthreads();
    if (d < NPART) sm_w[d] = expf(sm_m[d]-M);
    __syncthreads();
    float pNew = expf(sNew - M);
    float L = pNew;
    #pragma unroll 8
    for (int i2=0;i2<NPART;i2++) L += sm_l[i2]*sm_w[i2];
    const float* pc = g_pctx + (size_t)bh*NPART*HD + d;
    float a = 0.f;
    #pragma unroll 4
    for (int i2=0;i2<NPART;i2++) a += sm_w[i2] * pc[(size_t)i2*HD];
    float vNew = g_v[base+d];
    a += pNew * vNew;
    float invL = 1.0f / L;
    g_ctx[bh*HD + d] = a * invL;
    if (d == 0) { g_m[bh] = M; g_il[bh] = invL; }
    // eviction output for the NEW token (roped k) -> keep slot 515
    size_t doff = ((size_t)bh*KEEP + (KEEP-1))*HD + d;
    out[OFF_K + doff] = kn;
    out[OFF_V + doff] = vNew;
}

// ---------------- 5. importance: mean over heads + prev ----------------
__global__ void k_imp(const float* __restrict__ prev) {
    int idx = blockIdx.x*256 + threadIdx.x;
    if (idx >= Bb*KV) return;
    int b = idx / KV, s = idx % KV;
    float v = 0.f;
    #pragma unroll 4
    for (int h=0; h<Hh; h++) {
        int bh = b*Hh + h;
        v += __expf(g_scores[(size_t)bh*SSTR + s] - g_m[bh]) * g_il[bh];
    }
    v *= (1.0f/32.0f);
    if (s < Ss) v += prev[b*Ss + s];
    g_imp[idx] = v;
}

// ---------------- 6. per-batch: top-4 + imp_kept + top-4 K/V gather ----------------
__global__ void k_topk(const float* __restrict__ Kc, const float* __restrict__ Vc,
                       float* __restrict__ out) {
    int b = blockIdx.x;
    int tid = threadIdx.x;                 // 256 threads
    const float* imp = g_imp + b*KV;
    float bv[4]; int bi[4];
    #pragma unroll
    for (int r=0;r<4;r++){ bv[r]=-1e30f; bi[r]=0x7FFFFFFF; }
    for (int s = tid; s < CAND; s += 256) ins4(imp[s], s, bv, bi);

    __shared__ float sv[1024];
    __shared__ int   si[1024];
    __shared__ int   tk[4];
    #pragma unroll
    for (int r=0;r<4;r++){ sv[tid*4+r]=bv[r]; si[tid*4+r]=bi[r]; }
    __syncthreads();

    if (tid < 32) {
        float mv[4]; int mi[4];
        #pragma unroll
        for (int r=0;r<4;r++){ mv[r]=-1e30f; mi[r]=0x7FFFFFFF; }
        for (int t = tid; t < 256; t += 32)
            #pragma unroll
            for (int r=0;r<4;r++) ins4(sv[t*4+r], si[t*4+r], mv, mi);
        #pragma unroll
        for (int r=0;r<4;r++){ sv[tid*4+r]=mv[r]; si[tid*4+r]=mi[r]; }
    }
    __syncthreads();
    if (tid == 0) {
        float tv[4]; int ti[4];
        #pragma unroll
        for (int r=0;r<4;r++){ tv[r]=-1e30f; ti[r]=0x7FFFFFFF; }
        for (int e=0;e<128;e++) ins4(sv[e], si[e], tv, ti);
        #pragma unroll
        for (int a=0;a<4;a++)
            #pragma unroll
            for (int c2=a+1;c2<4;c2++)
                if (ti[c2] < ti[a]) { int t=ti[a]; ti[a]=ti[c2]; ti[c2]=t; }
        #pragma unroll
        for (int r=0;r<4;r++) { g_topk[b*4+r] = ti[r]; tk[r] = ti[r]; }
    }
    __syncthreads();

    for (int j = tid; j < KEEP; j += 256) {
        int idx = (j < 4) ? tk[j] : (CAND + (j-4));
        out[OFF_IMP + b*KEEP + j] = g_imp[b*KV + idx];
    }

    for (int t = tid; t < 4096; t += 256) {
        int h    = t >> 7;
        int r    = (t >> 5) & 3;
        int lane = t & 31;
        int bh   = b*Hh + h;
        int idx  = tk[r];
        size_t soff = ((size_t)bh*Ss + idx)*32 + lane;
        size_t doff = ((size_t)bh*KEEP + r)*32 + lane;
        ((float4*)(out + OFF_K))[doff] = ((const float4*)Kc)[soff];
        ((float4*)(out + OFF_V))[doff] = ((const float4*)Vc)[soff];
    }
}

// ---------------- 7. output projection: attn_out = ctx @ Wo ----------------
__global__ void k_oproj(const float* __restrict__ Wo, float* __restrict__ out) {
    __shared__ float h_sm[Bb*KC];
    int i0 = blockIdx.y * KC;
    int j  = blockIdx.x * 512 + threadIdx.x * 4;
    for (int idx = threadIdx.x; idx < Bb*KC; idx += blockDim.x)
        h_sm[idx] = g_ctx[(idx/KC)*Dd + i0 + (idx%KC)];
    __syncthreads();
    float4 acc[Bb];
    #pragma unroll
    for (int b=0;b<Bb;b++) acc[b] = make_float4(0.f,0.f,0.f,0.f);
    const float4* Wp = (const float4*)(Wo + (size_t)i0*Dd + j);
    for (int ii=0; ii<KC; ii+=4) {
        float4 w0 = __ldcs(&Wp[(size_t)(ii+0)*(Dd/4)]);
        float4 w1 = __ldcs(&Wp[(size_t)(ii+1)*(Dd/4)]);
        float4 w2 = __ldcs(&Wp[(size_t)(ii+2)*(Dd/4)]);
        float4 w3 = __ldcs(&Wp[(size_t)(ii+3)*(Dd/4)]);
        #pragma unroll
        for (int b=0;b<Bb;b++) {
            float h0 = h_sm[b*KC+ii+0], h1 = h_sm[b*KC+ii+1];
            float h2 = h_sm[b*KC+ii+2], h3 = h_sm[b*KC+ii+3];
            acc[b].x += h0*w0.x + h1*w1.x + h2*w2.x + h3*w3.x;
            acc[b].y += h0*w0.y + h1*w1.y + h2*w2.y + h3*w3.y;
            acc[b].z += h0*w0.z + h1*w1.z + h2*w2.z + h3*w3.z;
            acc[b].w += h0*w0.w + h1*w1.w + h2*w2.w + h3*w3.w;
        }
    }
    #pragma unroll
    for (int b=0;b<Bb;b++) {
        atomicAdd(&out[b*Dd+j  ], acc[b].x);
        atomicAdd(&out[b*Dd+j+1], acc[b].y);
        atomicAdd(&out[b*Dd+j+2], acc[b].z);
        atomicAdd(&out[b*Dd+j+3], acc[b].w);
    }
}

// ---------------- stream/event resources (created at static init, NOT in launch) -----
namespace {
struct Resources {
    cudaStream_t sB;
    cudaEvent_t evA, evB, evComb, evC;
    Resources() {
        cudaStreamCreateWithFlags(&sB, cudaStreamNonBlocking);
        cudaEventCreateWithFlags(&evA,    cudaEventDisableTiming);
        cudaEventCreateWithFlags(&evB,    cudaEventDisableTiming);
        cudaEventCreateWithFlags(&evComb, cudaEventDisableTiming);
        cudaEventCreateWithFlags(&evC,    cudaEventDisableTiming);
    }
};
Resources R;
}

// ---------------- launch ----------------
extern "C" void kernel_launch(void* const* d_in, const int* in_sizes, int n_in,
                              void* d_out, int out_size) {
    const float* hs   = (const float*)d_in[0];
    const float* pk   = (const float*)d_in[1];
    const float* pv   = (const float*)d_in[2];
    const float* Wq   = (const float*)d_in[3];
    const float* Wk   = (const float*)d_in[4];
    const float* Wv   = (const float*)d_in[5];
    const float* Wo   = (const float*)d_in[6];
    const float* prev = (const float*)d_in[7];
    float* out = (float*)d_out;

    // main stream: zero -> projQ -> fused -> comb -> imp -> topk
    k_zero<<<(Bb*Dd + 255)/256, 256>>>(out);
    cudaEventRecord(R.evA, 0);

    // side stream: projK + projV overlap with fused
    cudaStreamWaitEvent(R.sB, R.evA, 0);
    k_projKV<<<dim3(Dd/512, Dd/KC, 2), 128, 0, R.sB>>>(hs, Wk, Wv);
    cudaEventRecord(R.evB, R.sB);

    k_projQ<<<dim3(Dd/512, Dd/KC), 128>>>(hs, Wq);
    k_fused<<<dim3(8, Bb*Hh), 256>>>(pk, pv, out);

    cudaStreamWaitEvent(0, R.evB, 0);          // comb needs g_k, g_v
    k_comb<<<Bb*Hh, 128>>>(out);
    cudaEventRecord(R.evComb, 0);

    k_imp<<<(Bb*KV + 255)/256, 256>>>(prev);
    k_topk<<<Bb, 256>>>(pk, pv, out);

    // side stream: oproj overlaps imp+topk
    cudaStreamWaitEvent(R.sB, R.evComb, 0);
    k_oproj<<<dim3(Dd/512, Dd/KC), 128, 0, R.sB>>>(Wo, out);
    cudaEventRecord(R.evC, R.sB);
    cudaStreamWaitEvent(0, R.evC, 0);
}

// round 12
// speedup vs baseline: 1.2502x; 1.2502x over previous
#include <cuda_runtime.h>
#include <math.h>

#define Bb   8
#define Hh   32
#define Ss   4096
#define HD   128
#define Dd   4096
#define KV   4097          // Ss + 1 new token
#define SSTR 4112          // padded score stride
#define CAND 3585          // KV - RECENT(512)
#define KEEP 516           // IMP_SIZE(4) + RECENT(512)
#define KC   64            // split-K chunk for projections
#define NPART 64           // split-K partials per (b,h): 8 chunks x 8 warps
#define NCHK 17            // imp chunks per batch (17*256 >= KV)

#define OFF_K   32768
#define OFF_V   (32768 + 16908288)
#define OFF_IMP (32768 + 2*16908288)

// ---------------- static scratch (no allocations allowed) ----------------
__device__ float g_q[Bb*Dd];
__device__ float g_k[Bb*Dd];
__device__ float g_v[Bb*Dd];
__device__ float g_scores[Bb*Hh*SSTR];
__device__ float g_m[Bb*Hh];
__device__ float g_il[Bb*Hh];        // 1/l
__device__ float g_ctx[Bb*Hh*HD];    // == Bb*Dd floats
__device__ float g_imp[Bb*KV];
__device__ int   g_topk[Bb*4];
__device__ float g_pm[Bb*Hh*NPART];
__device__ float g_pl[Bb*Hh*NPART];
__device__ float g_pctx[Bb*Hh*NPART*HD];   // 8 MB partial ctx
__device__ float g_cos[64];
__device__ float g_sin[64];
__device__ float g_bv[Bb*NCHK*4];          // per-chunk top4 values
__device__ int   g_bi[Bb*NCHK*4];          // per-chunk top4 indices

__device__ __forceinline__ bool better(float v1, int i1, float v2, int i2) {
    return (v1 > v2) || (v1 == v2 && i1 < i2);
}
__device__ __forceinline__ void ins4(float v, int i, float* bv, int* bi) {
    #pragma unroll
    for (int r=0;r<4;r++) {
        if (better(v, i, bv[r], bi[r])) {
            #pragma unroll
            for (int q=3;q>r;q--){ bv[q]=bv[q-1]; bi[q]=bi[q-1]; }
            bv[r]=v; bi[r]=i; return;
        }
    }
}

// ---------------- 1. zero accumulators + rope table ----------------
__global__ void k_zero(float* out0) {
    int i = blockIdx.x*blockDim.x + threadIdx.x;
    if (i < Bb*Dd) { g_q[i]=0.f; g_k[i]=0.f; g_v[i]=0.f; out0[i]=0.f; }
    if (blockIdx.x == 0 && threadIdx.x < 64) {
        double ang = 4096.0 * pow(10000.0, -(double)(2*threadIdx.x)/128.0);
        g_cos[threadIdx.x] = (float)cos(ang);
        g_sin[threadIdx.x] = (float)sin(ang);
    }
}

// ---------------- 2. QKV projection (z selects matrix; outputs are device globals) ----
__global__ void k_projQKV(const float* __restrict__ hs,
                          const float* __restrict__ Wq,
                          const float* __restrict__ Wk,
                          const float* __restrict__ Wv) {
    __shared__ float h_sm[Bb*KC];
    const float* W = (blockIdx.z==0) ? Wq : ((blockIdx.z==1) ? Wk : Wv);
    float* dst     = (blockIdx.z==0) ? g_q : ((blockIdx.z==1) ? g_k : g_v);
    int i0 = blockIdx.y * KC;
    int j  = blockIdx.x * 512 + threadIdx.x * 4;

    for (int idx = threadIdx.x; idx < Bb*KC; idx += blockDim.x)
        h_sm[idx] = hs[(idx/KC)*Dd + i0 + (idx%KC)];
    __syncthreads();

    float4 acc[Bb];
    #pragma unroll
    for (int b=0;b<Bb;b++) acc[b] = make_float4(0.f,0.f,0.f,0.f);

    const float4* Wp = (const float4*)(W + (size_t)i0*Dd + j);
    for (int ii=0; ii<KC; ii+=4) {
        float4 w0 = __ldcs(&Wp[(size_t)(ii+0)*(Dd/4)]);
        float4 w1 = __ldcs(&Wp[(size_t)(ii+1)*(Dd/4)]);
        float4 w2 = __ldcs(&Wp[(size_t)(ii+2)*(Dd/4)]);
        float4 w3 = __ldcs(&Wp[(size_t)(ii+3)*(Dd/4)]);
        #pragma unroll
        for (int b=0;b<Bb;b++) {
            float h0 = h_sm[b*KC+ii+0], h1 = h_sm[b*KC+ii+1];
            float h2 = h_sm[b*KC+ii+2], h3 = h_sm[b*KC+ii+3];
            acc[b].x += h0*w0.x + h1*w1.x + h2*w2.x + h3*w3.x;
            acc[b].y += h0*w0.y + h1*w1.y + h2*w2.y + h3*w3.y;
            acc[b].z += h0*w0.z + h1*w1.z + h2*w2.z + h3*w3.z;
            acc[b].w += h0*w0.w + h1*w1.w + h2*w2.w + h3*w3.w;
        }
    }
    #pragma unroll
    for (int b=0;b<Bb;b++) {
        atomicAdd(&dst[b*Dd+j  ], acc[b].x);
        atomicAdd(&dst[b*Dd+j+1], acc[b].y);
        atomicAdd(&dst[b*Dd+j+2], acc[b].z);
        atomicAdd(&dst[b*Dd+j+3], acc[b].w);
    }
}

// ---------------- 3. fused scores + online-softmax ctx + recent evict (q roped inline) ----
// grid (8, Bb*Hh), 256 threads (8 warps). warp handles 64 contiguous tokens.
__global__ void k_fused(const float* __restrict__ Kc, const float* __restrict__ Vc,
                        float* __restrict__ out) {
    int bh   = blockIdx.y;
    int warp = threadIdx.x >> 5, lane = threadIdx.x & 31;
    int s0   = blockIdx.x*512 + warp*64;
    float4 q4 = ((const float4*)(g_q + (bh/Hh)*Dd + (bh%Hh)*HD))[lane];
    // inline RoPE on q: partner lane is lane^16 (dims +-64)
    {
        float4 p4;
        p4.x = __shfl_xor_sync(0xFFFFFFFFu, q4.x, 16);
        p4.y = __shfl_xor_sync(0xFFFFFFFFu, q4.y, 16);
        p4.z = __shfl_xor_sync(0xFFFFFFFFu, q4.z, 16);
        p4.w = __shfl_xor_sync(0xFFFFFFFFu, q4.w, 16);
        float sign = (lane < 16) ? -1.f : 1.f;
        int i0 = (4*lane) & 63;
        float c0=g_cos[i0],   s0r=g_sin[i0];
        float c1=g_cos[i0+1], s1=g_sin[i0+1];
        float c2=g_cos[i0+2], s2=g_sin[i0+2];
        float c3=g_cos[i0+3], s3=g_sin[i0+3];
        q4.x = q4.x*c0 + sign*p4.x*s0r;
        q4.y = q4.y*c1 + sign*p4.y*s1;
        q4.z = q4.z*c2 + sign*p4.z*s2;
        q4.w = q4.w*c3 + sign*p4.w*s3;
    }
    const float4* Kp = (const float4*)Kc + (size_t)bh*Ss*32;
    const float4* Vp = (const float4*)Vc + (size_t)bh*Ss*32;
    float4* outK = (float4*)(out + OFF_K) + (size_t)bh*KEEP*32 + lane;
    float4* outV = (float4*)(out + OFF_V) + (size_t)bh*KEEP*32 + lane;
    float* sc = g_scores + (size_t)bh*SSTR;
    const float scale = 0.08838834764831845f;

    float m = -1e30f, l = 0.f;
    float4 acc = make_float4(0.f,0.f,0.f,0.f);

    for (int s = s0; s < s0+64; s += 4) {
        float4 k0 = Kp[(size_t)(s+0)*32 + lane];
        float4 k1 = Kp[(size_t)(s+1)*32 + lane];
        float4 k2 = Kp[(size_t)(s+2)*32 + lane];
        float4 k3 = Kp[(size_t)(s+3)*32 + lane];
        float4 v0 = Vp[(size_t)(s+0)*32 + lane];
        float4 v1 = Vp[(size_t)(s+1)*32 + lane];
        float4 v2 = Vp[(size_t)(s+2)*32 + lane];
        float4 v3 = Vp[(size_t)(s+3)*32 + lane];
        float d0 = q4.x*k0.x + q4.y*k0.y + q4.z*k0.z + q4.w*k0.w;
        float d1 = q4.x*k1.x + q4.y*k1.y + q4.z*k1.z + q4.w*k1.w;
        float d2 = q4.x*k2.x + q4.y*k2.y + q4.z*k2.z + q4.w*k2.w;
        float d3 = q4.x*k3.x + q4.y*k3.y + q4.z*k3.z + q4.w*k3.w;
        #pragma unroll
        for (int off=16; off; off>>=1) {
            d0 += __shfl_xor_sync(0xFFFFFFFFu, d0, off);
            d1 += __shfl_xor_sync(0xFFFFFFFFu, d1, off);
            d2 += __shfl_xor_sync(0xFFFFFFFFu, d2, off);
            d3 += __shfl_xor_sync(0xFFFFFFFFu, d3, off);
        }
        d0 *= scale; d1 *= scale; d2 *= scale; d3 *= scale;
        if (lane == 0) { sc[s]=d0; sc[s+1]=d1; sc[s+2]=d2; sc[s+3]=d3; }
        // recent-window eviction copy: tokens [CAND, Ss) -> keep slot 4 + (tok-CAND)
        if (s+3 >= CAND) {
            if (s+0 >= CAND) { outK[(size_t)(s+0-CAND+4)*32]=k0; outV[(size_t)(s+0-CAND+4)*32]=v0; }
            if (s+1 >= CAND) { outK[(size_t)(s+1-CAND+4)*32]=k1; outV[(size_t)(s+1-CAND+4)*32]=v1; }
            { outK[(size_t)(s+2-CAND+4)*32]=k2; outV[(size_t)(s+2-CAND+4)*32]=v2; }
            { outK[(size_t)(s+3-CAND+4)*32]=k3; outV[(size_t)(s+3-CAND+4)*32]=v3; }
        }
        float gm = fmaxf(m, fmaxf(fmaxf(d0,d1), fmaxf(d2,d3)));
        float r  = expf(m - gm);
        float p0 = expf(d0-gm), p1 = expf(d1-gm);
        float p2 = expf(d2-gm), p3 = expf(d3-gm);
        l = l*r + (p0+p1) + (p2+p3);
        acc.x = acc.x*r + p0*v0.x + p1*v1.x + p2*v2.x + p3*v3.x;
        acc.y = acc.y*r + p0*v0.y + p1*v1.y + p2*v2.y + p3*v3.y;
        acc.z = acc.z*r + p0*v0.z + p1*v1.z + p2*v2.z + p3*v3.z;
        acc.w = acc.w*r + p0*v0.w + p1*v1.w + p2*v2.w + p3*v3.w;
        m = gm;
    }
    int pid = bh*NPART + blockIdx.x*8 + warp;
    if (lane == 0) { g_pm[pid] = m; g_pl[pid] = l; }
    ((float4*)g_pctx)[(size_t)pid*32 + lane] = acc;
}

// ---------------- 4. combine: rope q/k, new-token score, merge partials, evict slot 515 ----
__global__ void k_comb(float* __restrict__ out) {
    int bh = blockIdx.x;
    int d  = threadIdx.x;                  // 128 threads
    __shared__ float sq[HD], sk[HD], red[HD];
    __shared__ float sm_m[NPART], sm_l[NPART], sm_w[NPART];
    int base = (bh/Hh)*Dd + (bh%Hh)*HD;
    sq[d] = g_q[base+d]; sk[d] = g_k[base+d];
    if (d < NPART) { sm_m[d] = g_pm[bh*NPART+d]; sm_l[d] = g_pl[bh*NPART+d]; }
    __syncthreads();
    int i = d & 63;
    float c = g_cos[i], s = g_sin[i];
    float qr = (d<64) ? -sq[d+64] : sq[d-64];
    float kr = (d<64) ? -sk[d+64] : sk[d-64];
    float qn = sq[d]*c + qr*s;
    float kn = sk[d]*c + kr*s;
    red[d] = qn*kn;
    __syncthreads();
    for (int st=64; st>0; st>>=1) { if (d<st) red[d]+=red[d+st]; __syncthreads(); }
    float sNew = red[0] * 0.08838834764831845f;
    if (d == 0) g_scores[(size_t)bh*SSTR + Ss] = sNew;

    float M = sNew;
    #pragma unroll 8
    for (int i2=0;i2<NPART;i2++) M = fmaxf(M, sm_m[i2]);
    __syncthreads();
    if (d < NPART) sm_w[d] = expf(sm_m[d]-M);
    __syncthreads();
    float pNew = expf(sNew - M);
    float L = pNew;
    #pragma unroll 8
    for (int i2=0;i2<NPART;i2++) L += sm_l[i2]*sm_w[i2];
    const float* pc = g_pctx + (size_t)bh*NPART*HD + d;
    float a = 0.f;
    #pragma unroll 4
    for (int i2=0;i2<NPART;i2++) a += sm_w[i2] * pc[(size_t)i2*HD];
    float vNew = g_v[base+d];
    a += pNew * vNew;
    float invL = 1.0f / L;
    g_ctx[bh*HD + d] = a * invL;
    if (d == 0) { g_m[bh] = M; g_il[bh] = invL; }
    // eviction output for the NEW token (roped k) -> keep slot 515
    size_t doff = ((size_t)bh*KEEP + (KEEP-1))*HD + d;
    out[OFF_K + doff] = kn;
    out[OFF_V + doff] = vNew;
}

// ---------------- 5. importance + per-chunk top-4 ----------------
// grid (NCHK, Bb), 256 threads. Each block = one 256-token chunk of one batch.
__global__ void k_imp(const float* __restrict__ prev) {
    int b   = blockIdx.y;
    int tid = threadIdx.x;
    int s   = blockIdx.x*256 + tid;
    float v = -1e30f;
    if (s < KV) {
        v = 0.f;
        #pragma unroll 4
        for (int h=0; h<Hh; h++) {
            int bh = b*Hh + h;
            v += __expf(g_scores[(size_t)bh*SSTR + s] - g_m[bh]) * g_il[bh];
        }
        v *= (1.0f/32.0f);
        if (s < Ss) v += prev[b*Ss + s];
        g_imp[b*KV + s] = v;
    }
    // block top4 over candidates (s < CAND)
    __shared__ float sv[256];
    __shared__ int   si[256];
    sv[tid] = (s < CAND) ? v : -1e30f;
    si[tid] = (s < CAND) ? s : 0x7FFFFFFF;
    __syncthreads();
    if (tid < 32) {
        float mv[4]; int mi[4];
        #pragma unroll
        for (int r=0;r<4;r++){ mv[r]=-1e30f; mi[r]=0x7FFFFFFF; }
        #pragma unroll
        for (int t=0;t<8;t++) ins4(sv[tid*8+t], si[tid*8+t], mv, mi);
        __syncwarp();
        #pragma unroll
        for (int r=0;r<4;r++){ sv[tid*4+r]=mv[r]; si[tid*4+r]=mi[r]; }
        __syncwarp();
        if (tid == 0) {
            float tv[4]; int ti[4];
            #pragma unroll
            for (int r=0;r<4;r++){ tv[r]=-1e30f; ti[r]=0x7FFFFFFF; }
            for (int e=0;e<128;e++) ins4(sv[e], si[e], tv, ti);
            int o = (b*NCHK + blockIdx.x)*4;
            #pragma unroll
            for (int r=0;r<4;r++){ g_bv[o+r]=tv[r]; g_bi[o+r]=ti[r]; }
        }
    }
}

// ---------------- 6. per-batch: merge chunk top4 + imp_kept + top-4 K/V gather ----------
__global__ void k_topk(const float* __restrict__ Kc, const float* __restrict__ Vc,
                       float* __restrict__ out) {
    int b = blockIdx.x;
    int tid = threadIdx.x;                 // 256 threads
    __shared__ int tk[4];
    if (tid == 0) {
        float tv[4]; int ti[4];
        #pragma unroll
        for (int r=0;r<4;r++){ tv[r]=-1e30f; ti[r]=0x7FFFFFFF; }
        for (int e=0;e<NCHK*4;e++) ins4(g_bv[b*NCHK*4+e], g_bi[b*NCHK*4+e], tv, ti);
        #pragma unroll
        for (int a=0;a<4;a++)
            #pragma unroll
            for (int c2=a+1;c2<4;c2++)
                if (ti[c2] < ti[a]) { int t=ti[a]; ti[a]=ti[c2]; ti[c2]=t; }
        #pragma unroll
        for (int r=0;r<4;r++) { g_topk[b*4+r] = ti[r]; tk[r] = ti[r]; }
    }
    __syncthreads();

    for (int j = tid; j < KEEP; j += 256) {
        int idx = (j < 4) ? tk[j] : (CAND + (j-4));
        out[OFF_IMP + b*KEEP + j] = g_imp[b*KV + idx];
    }

    for (int t = tid; t < 4096; t += 256) {
        int h    = t >> 7;
        int r    = (t >> 5) & 3;
        int lane = t & 31;
        int bh   = b*Hh + h;
        int idx  = tk[r];
        size_t soff = ((size_t)bh*Ss + idx)*32 + lane;
        size_t doff = ((size_t)bh*KEEP + r)*32 + lane;
        ((float4*)(out + OFF_K))[doff] = ((const float4*)Kc)[soff];
        ((float4*)(out + OFF_V))[doff] = ((const float4*)Vc)[soff];
    }
}

// ---------------- 7. output projection: attn_out = ctx @ Wo ----------------
__global__ void k_oproj(const float* __restrict__ Wo, float* __restrict__ out) {
    __shared__ float h_sm[Bb*KC];
    int i0 = blockIdx.y * KC;
    int j  = blockIdx.x * 512 + threadIdx.x * 4;
    for (int idx = threadIdx.x; idx < Bb*KC; idx += blockDim.x)
        h_sm[idx] = g_ctx[(idx/KC)*Dd + i0 + (idx%KC)];
    __syncthreads();
    float4 acc[Bb];
    #pragma unroll
    for (int b=0;b<Bb;b++) acc[b] = make_float4(0.f,0.f,0.f,0.f);
    const float4* Wp = (const float4*)(Wo + (size_t)i0*Dd + j);
    for (int ii=0; ii<KC; ii+=4) {
        float4 w0 = __ldcs(&Wp[(size_t)(ii+0)*(Dd/4)]);
        float4 w1 = __ldcs(&Wp[(size_t)(ii+1)*(Dd/4)]);
        float4 w2 = __ldcs(&Wp[(size_t)(ii+2)*(Dd/4)]);
        float4 w3 = __ldcs(&Wp[(size_t)(ii+3)*(Dd/4)]);
        #pragma unroll
        for (int b=0;b<Bb;b++) {
            float h0 = h_sm[b*KC+ii+0], h1 = h_sm[b*KC+ii+1];
            float h2 = h_sm[b*KC+ii+2], h3 = h_sm[b*KC+ii+3];
            acc[b].x += h0*w0.x + h1*w1.x + h2*w2.x + h3*w3.x;
            acc[b].y += h0*w0.y + h1*w1.y + h2*w2.y + h3*w3.y;
            acc[b].z += h0*w0.z + h1*w1.z + h2*w2.z + h3*w3.z;
            acc[b].w += h0*w0.w + h1*w1.w + h2*w2.w + h3*w3.w;
        }
    }
    #pragma unroll
    for (int b=0;b<Bb;b++) {
        atomicAdd(&out[b*Dd+j  ], acc[b].x);
        atomicAdd(&out[b*Dd+j+1], acc[b].y);
        atomicAdd(&out[b*Dd+j+2], acc[b].z);
        atomicAdd(&out[b*Dd+j+3], acc[b].w);
    }
}

// ---------------- launch (single stream — overlap regressed at LTS cap) ---------------
extern "C" void kernel_launch(void* const* d_in, const int* in_sizes, int n_in,
                              void* d_out, int out_size) {
    const float* hs   = (const float*)d_in[0];
    const float* pk   = (const float*)d_in[1];
    const float* pv   = (const float*)d_in[2];
    const float* Wq   = (const float*)d_in[3];
    const float* Wk   = (const float*)d_in[4];
    const float* Wv   = (const float*)d_in[5];
    const float* Wo   = (const float*)d_in[6];
    const float* prev = (const float*)d_in[7];
    float* out = (float*)d_out;

    k_zero   <<<(Bb*Dd + 255)/256, 256>>>(out);
    k_projQKV<<<dim3(Dd/512, Dd/KC, 3), 128>>>(hs, Wq, Wk, Wv);
    k_fused  <<<dim3(8, Bb*Hh), 256>>>(pk, pv, out);
    k_comb   <<<Bb*Hh, 128>>>(out);
    k_imp    <<<dim3(NCHK, Bb), 256>>>(prev);
    k_topk   <<<Bb, 256>>>(pk, pv, out);
    k_oproj  <<<dim3(Dd/512, Dd/KC), 128>>>(Wo, out);
}

// round 13
// speedup vs baseline: 1.2708x; 1.0165x over previous
#include <cuda_runtime.h>
#include <math.h>

#define Bb   8
#define Hh   32
#define Ss   4096
#define HD   128
#define Dd   4096
#define KV   4097          // Ss + 1 new token
#define SSTR 4112          // padded score stride
#define CAND 3585          // KV - RECENT(512)
#define KEEP 516           // IMP_SIZE(4) + RECENT(512)
#define KC   64            // split-K chunk for projections
#define NPART 64           // split-K partials per (b,h): 8 chunks x 8 warps
#define NCHK 17            // imp chunks per batch (17*256 >= KV)

#define OFF_K   32768
#define OFF_V   (32768 + 16908288)
#define OFF_IMP (32768 + 2*16908288)

// ---------------- static scratch (no allocations allowed) ----------------
__device__ float g_q[Bb*Dd];
__device__ float g_k[Bb*Dd];
__device__ float g_v[Bb*Dd];
__device__ float g_scores[Bb*Hh*SSTR];
__device__ float g_m[Bb*Hh];
__device__ float g_il[Bb*Hh];        // 1/l
__device__ float g_ctx[Bb*Hh*HD];    // == Bb*Dd floats
__device__ float g_imp[Bb*KV];
__device__ int   g_topk[Bb*4];
__device__ float g_pm[Bb*Hh*NPART];
__device__ float g_pl[Bb*Hh*NPART];
__device__ float g_pctx[Bb*Hh*NPART*HD];   // 8 MB partial ctx
__device__ float g_cos[64];
__device__ float g_sin[64];
__device__ float g_bv[Bb*NCHK*4];          // per-chunk top4 values
__device__ int   g_bi[Bb*NCHK*4];          // per-chunk top4 indices

__device__ __forceinline__ bool better(float v1, int i1, float v2, int i2) {
    return (v1 > v2) || (v1 == v2 && i1 < i2);
}
__device__ __forceinline__ void ins4(float v, int i, float* bv, int* bi) {
    #pragma unroll
    for (int r=0;r<4;r++) {
        if (better(v, i, bv[r], bi[r])) {
            #pragma unroll
            for (int q=3;q>r;q--){ bv[q]=bv[q-1]; bi[q]=bi[q-1]; }
            bv[r]=v; bi[r]=i; return;
        }
    }
}

// ---------------- 1. zero accumulators + rope table ----------------
__global__ void k_zero(float* out0) {
    int i = blockIdx.x*blockDim.x + threadIdx.x;
    if (i < Bb*Dd) { g_q[i]=0.f; g_k[i]=0.f; g_v[i]=0.f; out0[i]=0.f; }
    if (blockIdx.x == 0 && threadIdx.x < 64) {
        double ang = 4096.0 * pow(10000.0, -(double)(2*threadIdx.x)/128.0);
        g_cos[threadIdx.x] = (float)cos(ang);
        g_sin[threadIdx.x] = (float)sin(ang);
    }
}

// ---------------- 2. QKV projection (z selects matrix; outputs are device globals) ----
__global__ void k_projQKV(const float* __restrict__ hs,
                          const float* __restrict__ Wq,
                          const float* __restrict__ Wk,
                          const float* __restrict__ Wv) {
    __shared__ float h_sm[Bb*KC];
    const float* W = (blockIdx.z==0) ? Wq : ((blockIdx.z==1) ? Wk : Wv);
    float* dst     = (blockIdx.z==0) ? g_q : ((blockIdx.z==1) ? g_k : g_v);
    int i0 = blockIdx.y * KC;
    int j  = blockIdx.x * 512 + threadIdx.x * 4;

    for (int idx = threadIdx.x; idx < Bb*KC; idx += blockDim.x)
        h_sm[idx] = hs[(idx/KC)*Dd + i0 + (idx%KC)];
    __syncthreads();

    float4 acc[Bb];
    #pragma unroll
    for (int b=0;b<Bb;b++) acc[b] = make_float4(0.f,0.f,0.f,0.f);

    const float4* Wp = (const float4*)(W + (size_t)i0*Dd + j);
    for (int ii=0; ii<KC; ii+=4) {
        float4 w0 = __ldcs(&Wp[(size_t)(ii+0)*(Dd/4)]);
        float4 w1 = __ldcs(&Wp[(size_t)(ii+1)*(Dd/4)]);
        float4 w2 = __ldcs(&Wp[(size_t)(ii+2)*(Dd/4)]);
        float4 w3 = __ldcs(&Wp[(size_t)(ii+3)*(Dd/4)]);
        #pragma unroll
        for (int b=0;b<Bb;b++) {
            float h0 = h_sm[b*KC+ii+0], h1 = h_sm[b*KC+ii+1];
            float h2 = h_sm[b*KC+ii+2], h3 = h_sm[b*KC+ii+3];
            acc[b].x += h0*w0.x + h1*w1.x + h2*w2.x + h3*w3.x;
            acc[b].y += h0*w0.y + h1*w1.y + h2*w2.y + h3*w3.y;
            acc[b].z += h0*w0.z + h1*w1.z + h2*w2.z + h3*w3.z;
            acc[b].w += h0*w0.w + h1*w1.w + h2*w2.w + h3*w3.w;
        }
    }
    #pragma unroll
    for (int b=0;b<Bb;b++) {
        atomicAdd(&dst[b*Dd+j  ], acc[b].x);
        atomicAdd(&dst[b*Dd+j+1], acc[b].y);
        atomicAdd(&dst[b*Dd+j+2], acc[b].z);
        atomicAdd(&dst[b*Dd+j+3], acc[b].w);
    }
}

// ---------------- 3. fused scores + online-softmax ctx + recent evict (q roped inline) ----
// grid (8, Bb*Hh), 256 threads (8 warps). warp handles 64 contiguous tokens.
__global__ void k_fused(const float* __restrict__ Kc, const float* __restrict__ Vc,
                        float* __restrict__ out) {
    int bh   = blockIdx.y;
    int warp = threadIdx.x >> 5, lane = threadIdx.x & 31;
    int s0   = blockIdx.x*512 + warp*64;
    float4 q4 = ((const float4*)(g_q + (bh/Hh)*Dd + (bh%Hh)*HD))[lane];
    // inline RoPE on q: partner lane is lane^16 (dims +-64)
    {
        float4 p4;
        p4.x = __shfl_xor_sync(0xFFFFFFFFu, q4.x, 16);
        p4.y = __shfl_xor_sync(0xFFFFFFFFu, q4.y, 16);
        p4.z = __shfl_xor_sync(0xFFFFFFFFu, q4.z, 16);
        p4.w = __shfl_xor_sync(0xFFFFFFFFu, q4.w, 16);
        float sign = (lane < 16) ? -1.f : 1.f;
        int i0 = (4*lane) & 63;
        float c0=g_cos[i0],   s0r=g_sin[i0];
        float c1=g_cos[i0+1], s1=g_sin[i0+1];
        float c2=g_cos[i0+2], s2=g_sin[i0+2];
        float c3=g_cos[i0+3], s3=g_sin[i0+3];
        q4.x = q4.x*c0 + sign*p4.x*s0r;
        q4.y = q4.y*c1 + sign*p4.y*s1;
        q4.z = q4.z*c2 + sign*p4.z*s2;
        q4.w = q4.w*c3 + sign*p4.w*s3;
    }
    const float4* Kp = (const float4*)Kc + (size_t)bh*Ss*32;
    const float4* Vp = (const float4*)Vc + (size_t)bh*Ss*32;
    float4* outK = (float4*)(out + OFF_K) + (size_t)bh*KEEP*32 + lane;
    float4* outV = (float4*)(out + OFF_V) + (size_t)bh*KEEP*32 + lane;
    float* sc = g_scores + (size_t)bh*SSTR;
    const float scale = 0.08838834764831845f;

    float m = -1e30f, l = 0.f;
    float4 acc = make_float4(0.f,0.f,0.f,0.f);

    for (int s = s0; s < s0+64; s += 4) {
        float4 k0 = Kp[(size_t)(s+0)*32 + lane];
        float4 k1 = Kp[(size_t)(s+1)*32 + lane];
        float4 k2 = Kp[(size_t)(s+2)*32 + lane];
        float4 k3 = Kp[(size_t)(s+3)*32 + lane];
        float4 v0 = Vp[(size_t)(s+0)*32 + lane];
        float4 v1 = Vp[(size_t)(s+1)*32 + lane];
        float4 v2 = Vp[(size_t)(s+2)*32 + lane];
        float4 v3 = Vp[(size_t)(s+3)*32 + lane];
        // evict stores issued early: shortens k/v live ranges
        if (s+3 >= CAND) {
            if (s+0 >= CAND) { outK[(size_t)(s+0-CAND+4)*32]=k0; outV[(size_t)(s+0-CAND+4)*32]=v0; }
            if (s+1 >= CAND) { outK[(size_t)(s+1-CAND+4)*32]=k1; outV[(size_t)(s+1-CAND+4)*32]=v1; }
            { outK[(size_t)(s+2-CAND+4)*32]=k2; outV[(size_t)(s+2-CAND+4)*32]=v2; }
            { outK[(size_t)(s+3-CAND+4)*32]=k3; outV[(size_t)(s+3-CAND+4)*32]=v3; }
        }
        float d0 = q4.x*k0.x + q4.y*k0.y + q4.z*k0.z + q4.w*k0.w;
        float d1 = q4.x*k1.x + q4.y*k1.y + q4.z*k1.z + q4.w*k1.w;
        float d2 = q4.x*k2.x + q4.y*k2.y + q4.z*k2.z + q4.w*k2.w;
        float d3 = q4.x*k3.x + q4.y*k3.y + q4.z*k3.z + q4.w*k3.w;
        #pragma unroll
        for (int off=16; off; off>>=1) {
            d0 += __shfl_xor_sync(0xFFFFFFFFu, d0, off);
            d1 += __shfl_xor_sync(0xFFFFFFFFu, d1, off);
            d2 += __shfl_xor_sync(0xFFFFFFFFu, d2, off);
            d3 += __shfl_xor_sync(0xFFFFFFFFu, d3, off);
        }
        d0 *= scale; d1 *= scale; d2 *= scale; d3 *= scale;
        if (lane == 0) { sc[s]=d0; sc[s+1]=d1; sc[s+2]=d2; sc[s+3]=d3; }
        float gm = fmaxf(m, fmaxf(fmaxf(d0,d1), fmaxf(d2,d3)));
        float r  = expf(m - gm);
        float p0 = expf(d0-gm), p1 = expf(d1-gm);
        float p2 = expf(d2-gm), p3 = expf(d3-gm);
        l = l*r + (p0+p1) + (p2+p3);
        acc.x = acc.x*r + p0*v0.x + p1*v1.x + p2*v2.x + p3*v3.x;
        acc.y = acc.y*r + p0*v0.y + p1*v1.y + p2*v2.y + p3*v3.y;
        acc.z = acc.z*r + p0*v0.z + p1*v1.z + p2*v2.z + p3*v3.z;
        acc.w = acc.w*r + p0*v0.w + p1*v1.w + p2*v2.w + p3*v3.w;
        m = gm;
    }
    int pid = bh*NPART + blockIdx.x*8 + warp;
    if (lane == 0) { g_pm[pid] = m; g_pl[pid] = l; }
    ((float4*)g_pctx)[(size_t)pid*32 + lane] = acc;
}

// ---------------- 4. combine (512 thr, 4-way NPART split): rope q/k, score, merge, evict 515
__global__ void k_comb(float* __restrict__ out) {
    int bh  = blockIdx.x;
    int tid = threadIdx.x;                 // 512 threads
    int d   = tid & 127, part = tid >> 7;  // part 0..3
    __shared__ float sq[HD], sk[HD], red[HD];
    __shared__ float sm_m[NPART], sm_l[NPART], sm_w[NPART];
    __shared__ float psum[4*HD];
    int base = (bh/Hh)*Dd + (bh%Hh)*HD;
    if (part == 0) { sq[d] = g_q[base+d]; sk[d] = g_k[base+d]; }
    if (tid < NPART) { sm_m[tid] = g_pm[bh*NPART+tid]; sm_l[tid] = g_pl[bh*NPART+tid]; }
    __syncthreads();
    // rope q/k for the new token
    int i = d & 63;
    float c = g_cos[i], s = g_sin[i];
    float qr = (d<64) ? -sq[d+64] : sq[d-64];
    float kr = (d<64) ? -sk[d+64] : sk[d-64];
    float qn = sq[d]*c + qr*s;
    float kn = sk[d]*c + kr*s;
    if (part == 0) red[d] = qn*kn;
    __syncthreads();
    for (int st=64; st>0; st>>=1) { if (tid<st) red[tid]+=red[tid+st]; __syncthreads(); }
    float sNew = red[0] * 0.08838834764831845f;
    if (tid == 0) g_scores[(size_t)bh*SSTR + Ss] = sNew;

    float M = sNew;
    #pragma unroll 8
    for (int i2=0;i2<NPART;i2++) M = fmaxf(M, sm_m[i2]);
    __syncthreads();
    if (tid < NPART) sm_w[tid] = expf(sm_m[tid]-M);
    __syncthreads();
    float pNew = expf(sNew - M);
    float L = pNew;
    #pragma unroll 8
    for (int i2=0;i2<NPART;i2++) L += sm_l[i2]*sm_w[i2];

    // each part sums 16 of 64 partial-ctx rows for its d column
    const float* pc = g_pctx + (size_t)bh*NPART*HD + d;
    float a = 0.f;
    #pragma unroll 4
    for (int i2=part*16; i2<part*16+16; i2++) a += sm_w[i2] * pc[(size_t)i2*HD];
    psum[tid] = a;
    __syncthreads();
    if (part == 0) {
        float at = psum[d] + psum[128+d] + psum[256+d] + psum[384+d];
        float vNew = g_v[base+d];
        at += pNew * vNew;
        float invL = 1.0f / L;
        g_ctx[bh*HD + d] = at * invL;
        if (d == 0) { g_m[bh] = M; g_il[bh] = invL; }
        // eviction output for the NEW token (roped k) -> keep slot 515
        size_t doff = ((size_t)bh*KEEP + (KEEP-1))*HD + d;
        out[OFF_K + doff] = kn;
        out[OFF_V + doff] = vNew;
    }
}

// ---------------- 5. importance + per-chunk top-4 ----------------
// grid (NCHK, Bb), 256 threads. Each block = one 256-token chunk of one batch.
__global__ void k_imp(const float* __restrict__ prev) {
    int b   = blockIdx.y;
    int tid = threadIdx.x;
    int s   = blockIdx.x*256 + tid;
    float v = -1e30f;
    if (s < KV) {
        v = 0.f;
        #pragma unroll 4
        for (int h=0; h<Hh; h++) {
            int bh = b*Hh + h;
            v += __expf(g_scores[(size_t)bh*SSTR + s] - g_m[bh]) * g_il[bh];
        }
        v *= (1.0f/32.0f);
        if (s < Ss) v += prev[b*Ss + s];
        g_imp[b*KV + s] = v;
    }
    // block top4 over candidates (s < CAND)
    __shared__ float sv[256];
    __shared__ int   si[256];
    sv[tid] = (s < CAND) ? v : -1e30f;
    si[tid] = (s < CAND) ? s : 0x7FFFFFFF;
    __syncthreads();
    if (tid < 32) {
        float mv[4]; int mi[4];
        #pragma unroll
        for (int r=0;r<4;r++){ mv[r]=-1e30f; mi[r]=0x7FFFFFFF; }
        #pragma unroll
        for (int t=0;t<8;t++) ins4(sv[tid*8+t], si[tid*8+t], mv, mi);
        __syncwarp();
        #pragma unroll
        for (int r=0;r<4;r++){ sv[tid*4+r]=mv[r]; si[tid*4+r]=mi[r]; }
        __syncwarp();
        if (tid == 0) {
            float tv[4]; int ti[4];
            #pragma unroll
            for (int r=0;r<4;r++){ tv[r]=-1e30f; ti[r]=0x7FFFFFFF; }
            for (int e=0;e<128;e++) ins4(sv[e], si[e], tv, ti);
            int o = (b*NCHK + blockIdx.x)*4;
            #pragma unroll
            for (int r=0;r<4;r++){ g_bv[o+r]=tv[r]; g_bi[o+r]=ti[r]; }
        }
    }
}

// ---------------- 6. per-batch: merge chunk top4 + imp_kept + top-4 K/V gather ----------
__global__ void k_topk(const float* __restrict__ Kc, const float* __restrict__ Vc,
                       float* __restrict__ out) {
    int b = blockIdx.x;
    int tid = threadIdx.x;                 // 256 threads
    __shared__ int tk[4];
    if (tid == 0) {
        float tv[4]; int ti[4];
        #pragma unroll
        for (int r=0;r<4;r++){ tv[r]=-1e30f; ti[r]=0x7FFFFFFF; }
        for (int e=0;e<NCHK*4;e++) ins4(g_bv[b*NCHK*4+e], g_bi[b*NCHK*4+e], tv, ti);
        #pragma unroll
        for (int a=0;a<4;a++)
            #pragma unroll
            for (int c2=a+1;c2<4;c2++)
                if (ti[c2] < ti[a]) { int t=ti[a]; ti[a]=ti[c2]; ti[c2]=t; }
        #pragma unroll
        for (int r=0;r<4;r++) { g_topk[b*4+r] = ti[r]; tk[r] = ti[r]; }
    }
    __syncthreads();

    for (int j = tid; j < KEEP; j += 256) {
        int idx = (j < 4) ? tk[j] : (CAND + (j-4));
        out[OFF_IMP + b*KEEP + j] = g_imp[b*KV + idx];
    }

    for (int t = tid; t < 4096; t += 256) {
        int h    = t >> 7;
        int r    = (t >> 5) & 3;
        int lane = t & 31;
        int bh   = b*Hh + h;
        int idx  = tk[r];
        size_t soff = ((size_t)bh*Ss + idx)*32 + lane;
        size_t doff = ((size_t)bh*KEEP + r)*32 + lane;
        ((float4*)(out + OFF_K))[doff] = ((const float4*)Kc)[soff];
        ((float4*)(out + OFF_V))[doff] = ((const float4*)Vc)[soff];
    }
}

// ---------------- 7. output projection: attn_out = ctx @ Wo ----------------
__global__ void k_oproj(const float* __restrict__ Wo, float* __restrict__ out) {
    __shared__ float h_sm[Bb*KC];
    int i0 = blockIdx.y * KC;
    int j  = blockIdx.x * 512 + threadIdx.x * 4;
    for (int idx = threadIdx.x; idx < Bb*KC; idx += blockDim.x)
        h_sm[idx] = g_ctx[(idx/KC)*Dd + i0 + (idx%KC)];
    __syncthreads();
    float4 acc[Bb];
    #pragma unroll
    for (int b=0;b<Bb;b++) acc[b] = make_float4(0.f,0.f,0.f,0.f);
    const float4* Wp = (const float4*)(Wo + (size_t)i0*Dd + j);
    for (int ii=0; ii<KC; ii+=4) {
        float4 w0 = __ldcs(&Wp[(size_t)(ii+0)*(Dd/4)]);
        float4 w1 = __ldcs(&Wp[(size_t)(ii+1)*(Dd/4)]);
        float4 w2 = __ldcs(&Wp[(size_t)(ii+2)*(Dd/4)]);
        float4 w3 = __ldcs(&Wp[(size_t)(ii+3)*(Dd/4)]);
        #pragma unroll
        for (int b=0;b<Bb;b++) {
            float h0 = h_sm[b*KC+ii+0], h1 = h_sm[b*KC+ii+1];
            float h2 = h_sm[b*KC+ii+2], h3 = h_sm[b*KC+ii+3];
            acc[b].x += h0*w0.x + h1*w1.x + h2*w2.x + h3*w3.x;
            acc[b].y += h0*w0.y + h1*w1.y + h2*w2.y + h3*w3.y;
            acc[b].z += h0*w0.z + h1*w1.z + h2*w2.z + h3*w3.z;
            acc[b].w += h0*w0.w + h1*w1.w + h2*w2.w + h3*w3.w;
        }
    }
    #pragma unroll
    for (int b=0;b<Bb;b++) {
        atomicAdd(&out[b*Dd+j  ], acc[b].x);
        atomicAdd(&out[b*Dd+j+1], acc[b].y);
        atomicAdd(&out[b*Dd+j+2], acc[b].z);
        atomicAdd(&out[b*Dd+j+3], acc[b].w);
    }
}

// ---------------- launch (single stream) ----------------
extern "C" void kernel_launch(void* const* d_in, const int* in_sizes, int n_in,
                              void* d_out, int out_size) {
    const float* hs   = (const float*)d_in[0];
    const float* pk   = (const float*)d_in[1];
    const float* pv   = (const float*)d_in[2];
    const float* Wq   = (const float*)d_in[3];
    const float* Wk   = (const float*)d_in[4];
    const float* Wv   = (const float*)d_in[5];
    const float* Wo   = (const float*)d_in[6];
    const float* prev = (const float*)d_in[7];
    float* out = (float*)d_out;

    k_zero   <<<(Bb*Dd + 255)/256, 256>>>(out);
    k_projQKV<<<dim3(Dd/512, Dd/KC, 3), 128>>>(hs, Wq, Wk, Wv);
    k_fused  <<<dim3(8, Bb*Hh), 256>>>(pk, pv, out);
    k_comb   <<<Bb*Hh, 512>>>(out);
    k_imp    <<<dim3(NCHK, Bb), 256>>>(prev);
    k_topk   <<<Bb, 256>>>(pk, pv, out);
    k_oproj  <<<dim3(Dd/512, Dd/KC), 128>>>(Wo, out);
}

// round 14
// speedup vs baseline: 1.3282x; 1.0452x over previous
#include <cuda_runtime.h>
#include <math.h>

#define Bb   8
#define Hh   32
#define Ss   4096
#define HD   128
#define Dd   4096
#define KV   4097          // Ss + 1 new token
#define SSTR 4112          // padded score stride
#define CAND 3585          // KV - RECENT(512)
#define KEEP 516           // IMP_SIZE(4) + RECENT(512)
#define KC   64            // split-K chunk for projections
#define NPART 64           // split-K partials per (b,h): 8 chunks x 8 warps
#define NCHK 17            // imp chunks per batch (17*256 >= KV)
#define FBLK 2048          // fused blocks in mega kernel
#define PBLK 512           // proj blocks in mega kernel (256 K + 256 V)
#define IBLK 136           // imp blocks in impoproj (17*8)

#define OFF_K   32768
#define OFF_V   (32768 + 16908288)
#define OFF_IMP (32768 + 2*16908288)

// ---------------- static scratch (no allocations allowed) ----------------
__device__ float g_q[Bb*Dd];
__device__ float g_k[Bb*Dd];
__device__ float g_v[Bb*Dd];
__device__ float g_scores[Bb*Hh*SSTR];
__device__ float g_m[Bb*Hh];
__device__ float g_il[Bb*Hh];        // 1/l
__device__ float g_ctx[Bb*Hh*HD];    // == Bb*Dd floats
__device__ float g_imp[Bb*KV];
__device__ int   g_topk[Bb*4];
__device__ float g_pm[Bb*Hh*NPART];
__device__ float g_pl[Bb*Hh*NPART];
__device__ float g_pctx[Bb*Hh*NPART*HD];   // 8 MB partial ctx
__device__ float g_cos[64];
__device__ float g_sin[64];
__device__ float g_bv[Bb*NCHK*4];          // per-chunk top4 values
__device__ int   g_bi[Bb*NCHK*4];          // per-chunk top4 indices

__device__ __forceinline__ bool better(float v1, int i1, float v2, int i2) {
    return (v1 > v2) || (v1 == v2 && i1 < i2);
}
__device__ __forceinline__ void ins4(float v, int i, float* bv, int* bi) {
    #pragma unroll
    for (int r=0;r<4;r++) {
        if (better(v, i, bv[r], bi[r])) {
            #pragma unroll
            for (int q=3;q>r;q--){ bv[q]=bv[q-1]; bi[q]=bi[q-1]; }
            bv[r]=v; bi[r]=i; return;
        }
    }
}

// 256-thread GEMV body: out[b][j] += sum_{i0..i0+KC} h[b][i]*W[i][j], j-tile 1024
__device__ __forceinline__ void proj_body256(const float* __restrict__ hs,
                                             const float* __restrict__ W,
                                             float* dst, int i0, int jb,
                                             float* h_sm) {
    int j = jb*1024 + threadIdx.x*4;
    for (int idx = threadIdx.x; idx < Bb*KC; idx += 256)
        h_sm[idx] = hs[(idx/KC)*Dd + i0 + (idx%KC)];
    __syncthreads();

    float4 acc[Bb];
    #pragma unroll
    for (int b=0;b<Bb;b++) acc[b] = make_float4(0.f,0.f,0.f,0.f);

    const float4* Wp = (const float4*)(W + (size_t)i0*Dd + j);
    for (int ii=0; ii<KC; ii+=4) {
        float4 w0 = __ldcs(&Wp[(size_t)(ii+0)*(Dd/4)]);
        float4 w1 = __ldcs(&Wp[(size_t)(ii+1)*(Dd/4)]);
        float4 w2 = __ldcs(&Wp[(size_t)(ii+2)*(Dd/4)]);
        float4 w3 = __ldcs(&Wp[(size_t)(ii+3)*(Dd/4)]);
        #pragma unroll
        for (int b=0;b<Bb;b++) {
            float h0 = h_sm[b*KC+ii+0], h1 = h_sm[b*KC+ii+1];
            float h2 = h_sm[b*KC+ii+2], h3 = h_sm[b*KC+ii+3];
            acc[b].x += h0*w0.x + h1*w1.x + h2*w2.x + h3*w3.x;
            acc[b].y += h0*w0.y + h1*w1.y + h2*w2.y + h3*w3.y;
            acc[b].z += h0*w0.z + h1*w1.z + h2*w2.z + h3*w3.z;
            acc[b].w += h0*w0.w + h1*w1.w + h2*w2.w + h3*w3.w;
        }
    }
    #pragma unroll
    for (int b=0;b<Bb;b++) {
        atomicAdd(&dst[b*Dd+j  ], acc[b].x);
        atomicAdd(&dst[b*Dd+j+1], acc[b].y);
        atomicAdd(&dst[b*Dd+j+2], acc[b].z);
        atomicAdd(&dst[b*Dd+j+3], acc[b].w);
    }
}

// ---------------- 1. zero accumulators + rope table ----------------
__global__ void k_zero(float* out0) {
    int i = blockIdx.x*blockDim.x + threadIdx.x;
    if (i < Bb*Dd) { g_q[i]=0.f; g_k[i]=0.f; g_v[i]=0.f; out0[i]=0.f; }
    if (blockIdx.x == 0 && threadIdx.x < 64) {
        double ang = 4096.0 * pow(10000.0, -(double)(2*threadIdx.x)/128.0);
        g_cos[threadIdx.x] = (float)cos(ang);
        g_sin[threadIdx.x] = (float)sin(ang);
    }
}

// ---------------- 2. Q projection (128 thr, j-tile 512) ----------------
__global__ void k_projQ(const float* __restrict__ hs, const float* __restrict__ Wq) {
    __shared__ float h_sm[Bb*KC];
    int i0 = blockIdx.y * KC;
    int j  = blockIdx.x * 512 + threadIdx.x * 4;
    for (int idx = threadIdx.x; idx < Bb*KC; idx += blockDim.x)
        h_sm[idx] = hs[(idx/KC)*Dd + i0 + (idx%KC)];
    __syncthreads();
    float4 acc[Bb];
    #pragma unroll
    for (int b=0;b<Bb;b++) acc[b] = make_float4(0.f,0.f,0.f,0.f);
    const float4* Wp = (const float4*)(Wq + (size_t)i0*Dd + j);
    for (int ii=0; ii<KC; ii+=4) {
        float4 w0 = __ldcs(&Wp[(size_t)(ii+0)*(Dd/4)]);
        float4 w1 = __ldcs(&Wp[(size_t)(ii+1)*(Dd/4)]);
        float4 w2 = __ldcs(&Wp[(size_t)(ii+2)*(Dd/4)]);
        float4 w3 = __ldcs(&Wp[(size_t)(ii+3)*(Dd/4)]);
        #pragma unroll
        for (int b=0;b<Bb;b++) {
            float h0 = h_sm[b*KC+ii+0], h1 = h_sm[b*KC+ii+1];
            float h2 = h_sm[b*KC+ii+2], h3 = h_sm[b*KC+ii+3];
            acc[b].x += h0*w0.x + h1*w1.x + h2*w2.x + h3*w3.x;
            acc[b].y += h0*w0.y + h1*w1.y + h2*w2.y + h3*w3.y;
            acc[b].z += h0*w0.z + h1*w1.z + h2*w2.z + h3*w3.z;
            acc[b].w += h0*w0.w + h1*w1.w + h2*w2.w + h3*w3.w;
        }
    }
    #pragma unroll
    for (int b=0;b<Bb;b++) {
        atomicAdd(&g_q[b*Dd+j  ], acc[b].x);
        atomicAdd(&g_q[b*Dd+j+1], acc[b].y);
        atomicAdd(&g_q[b*Dd+j+2], acc[b].z);
        atomicAdd(&g_q[b*Dd+j+3], acc[b].w);
    }
}

// ---------------- 3. MEGA: fused attention (blocks 0..2047) + K/V proj (2048..2559) ----
__global__ void __launch_bounds__(256) k_mega(
        const float* __restrict__ Kc, const float* __restrict__ Vc,
        const float* __restrict__ hs,
        const float* __restrict__ Wk, const float* __restrict__ Wv,
        float* __restrict__ out) {
    int bid = blockIdx.x;
    if (bid >= FBLK) {
        // ---- K/V projection body ----
        __shared__ float h_sm[Bb*KC];
        int pid2 = bid - FBLK;             // 0..511
        const float* W = (pid2 < 256) ? Wk : Wv;
        float* dst     = (pid2 < 256) ? g_k : g_v;
        int rem = pid2 & 255;
        proj_body256(hs, W, dst, (rem >> 2)*KC, rem & 3, h_sm);
        return;
    }
    // ---- fused attention body ----
    int chunk = bid & 7;
    int bh    = bid >> 3;
    int warp = threadIdx.x >> 5, lane = threadIdx.x & 31;
    int s0   = chunk*512 + warp*64;
    float4 q4 = ((const float4*)(g_q + (bh/Hh)*Dd + (bh%Hh)*HD))[lane];
    // inline RoPE on q: partner lane is lane^16 (dims +-64)
    {
        float4 p4;
        p4.x = __shfl_xor_sync(0xFFFFFFFFu, q4.x, 16);
        p4.y = __shfl_xor_sync(0xFFFFFFFFu, q4.y, 16);
        p4.z = __shfl_xor_sync(0xFFFFFFFFu, q4.z, 16);
        p4.w = __shfl_xor_sync(0xFFFFFFFFu, q4.w, 16);
        float sign = (lane < 16) ? -1.f : 1.f;
        int i0 = (4*lane) & 63;
        float c0=g_cos[i0],   s0r=g_sin[i0];
        float c1=g_cos[i0+1], s1=g_sin[i0+1];
        float c2=g_cos[i0+2], s2=g_sin[i0+2];
        float c3=g_cos[i0+3], s3=g_sin[i0+3];
        q4.x = q4.x*c0 + sign*p4.x*s0r;
        q4.y = q4.y*c1 + sign*p4.y*s1;
        q4.z = q4.z*c2 + sign*p4.z*s2;
        q4.w = q4.w*c3 + sign*p4.w*s3;
    }
    const float4* Kp = (const float4*)Kc + (size_t)bh*Ss*32;
    const float4* Vp = (const float4*)Vc + (size_t)bh*Ss*32;
    float4* outK = (float4*)(out + OFF_K) + (size_t)bh*KEEP*32 + lane;
    float4* outV = (float4*)(out + OFF_V) + (size_t)bh*KEEP*32 + lane;
    float* sc = g_scores + (size_t)bh*SSTR;
    const float scale = 0.08838834764831845f;

    float m = -1e30f, l = 0.f;
    float4 acc = make_float4(0.f,0.f,0.f,0.f);

    for (int s = s0; s < s0+64; s += 4) {
        float4 k0 = Kp[(size_t)(s+0)*32 + lane];
        float4 k1 = Kp[(size_t)(s+1)*32 + lane];
        float4 k2 = Kp[(size_t)(s+2)*32 + lane];
        float4 k3 = Kp[(size_t)(s+3)*32 + lane];
        float4 v0 = Vp[(size_t)(s+0)*32 + lane];
        float4 v1 = Vp[(size_t)(s+1)*32 + lane];
        float4 v2 = Vp[(size_t)(s+2)*32 + lane];
        float4 v3 = Vp[(size_t)(s+3)*32 + lane];
        // evict stores issued early: shortens k/v live ranges
        if (s+3 >= CAND) {
            if (s+0 >= CAND) { outK[(size_t)(s+0-CAND+4)*32]=k0; outV[(size_t)(s+0-CAND+4)*32]=v0; }
            if (s+1 >= CAND) { outK[(size_t)(s+1-CAND+4)*32]=k1; outV[(size_t)(s+1-CAND+4)*32]=v1; }
            { outK[(size_t)(s+2-CAND+4)*32]=k2; outV[(size_t)(s+2-CAND+4)*32]=v2; }
            { outK[(size_t)(s+3-CAND+4)*32]=k3; outV[(size_t)(s+3-CAND+4)*32]=v3; }
        }
        float d0 = q4.x*k0.x + q4.y*k0.y + q4.z*k0.z + q4.w*k0.w;
        float d1 = q4.x*k1.x + q4.y*k1.y + q4.z*k1.z + q4.w*k1.w;
        float d2 = q4.x*k2.x + q4.y*k2.y + q4.z*k2.z + q4.w*k2.w;
        float d3 = q4.x*k3.x + q4.y*k3.y + q4.z*k3.z + q4.w*k3.w;
        #pragma unroll
        for (int off=16; off; off>>=1) {
            d0 += __shfl_xor_sync(0xFFFFFFFFu, d0, off);
            d1 += __shfl_xor_sync(0xFFFFFFFFu, d1, off);
            d2 += __shfl_xor_sync(0xFFFFFFFFu, d2, off);
            d3 += __shfl_xor_sync(0xFFFFFFFFu, d3, off);
        }
        d0 *= scale; d1 *= scale; d2 *= scale; d3 *= scale;
        if (lane == 0) { sc[s]=d0; sc[s+1]=d1; sc[s+2]=d2; sc[s+3]=d3; }
        float gm = fmaxf(m, fmaxf(fmaxf(d0,d1), fmaxf(d2,d3)));
        float r  = expf(m - gm);
        float p0 = expf(d0-gm), p1 = expf(d1-gm);
        float p2 = expf(d2-gm), p3 = expf(d3-gm);
        l = l*r + (p0+p1) + (p2+p3);
        acc.x = acc.x*r + p0*v0.x + p1*v1.x + p2*v2.x + p3*v3.x;
        acc.y = acc.y*r + p0*v0.y + p1*v1.y + p2*v2.y + p3*v3.y;
        acc.z = acc.z*r + p0*v0.z + p1*v1.z + p2*v2.z + p3*v3.z;
        acc.w = acc.w*r + p0*v0.w + p1*v1.w + p2*v2.w + p3*v3.w;
        m = gm;
    }
    int pid = bh*NPART + chunk*8 + warp;
    if (lane == 0) { g_pm[pid] = m; g_pl[pid] = l; }
    ((float4*)g_pctx)[(size_t)pid*32 + lane] = acc;
}

// ---------------- 4. combine (512 thr, 4-way NPART split): rope q/k, score, merge, evict 515
__global__ void k_comb(float* __restrict__ out) {
    int bh  = blockIdx.x;
    int tid = threadIdx.x;                 // 512 threads
    int d   = tid & 127, part = tid >> 7;  // part 0..3
    __shared__ float sq[HD], sk[HD], red[HD];
    __shared__ float sm_m[NPART], sm_l[NPART], sm_w[NPART];
    __shared__ float psum[4*HD];
    int base = (bh/Hh)*Dd + (bh%Hh)*HD;
    if (part == 0) { sq[d] = g_q[base+d]; sk[d] = g_k[base+d]; }
    if (tid < NPART) { sm_m[tid] = g_pm[bh*NPART+tid]; sm_l[tid] = g_pl[bh*NPART+tid]; }
    __syncthreads();
    // rope q/k for the new token
    int i = d & 63;
    float c = g_cos[i], s = g_sin[i];
    float qr = (d<64) ? -sq[d+64] : sq[d-64];
    float kr = (d<64) ? -sk[d+64] : sk[d-64];
    float qn = sq[d]*c + qr*s;
    float kn = sk[d]*c + kr*s;
    if (part == 0) red[d] = qn*kn;
    __syncthreads();
    for (int st=64; st>0; st>>=1) { if (tid<st) red[tid]+=red[tid+st]; __syncthreads(); }
    float sNew = red[0] * 0.08838834764831845f;
    if (tid == 0) g_scores[(size_t)bh*SSTR + Ss] = sNew;

    float M = sNew;
    #pragma unroll 8
    for (int i2=0;i2<NPART;i2++) M = fmaxf(M, sm_m[i2]);
    __syncthreads();
    if (tid < NPART) sm_w[tid] = expf(sm_m[tid]-M);
    __syncthreads();
    float pNew = expf(sNew - M);
    float L = pNew;
    #pragma unroll 8
    for (int i2=0;i2<NPART;i2++) L += sm_l[i2]*sm_w[i2];

    // each part sums 16 of 64 partial-ctx rows for its d column
    const float* pc = g_pctx + (size_t)bh*NPART*HD + d;
    float a = 0.f;
    #pragma unroll 4
    for (int i2=part*16; i2<part*16+16; i2++) a += sm_w[i2] * pc[(size_t)i2*HD];
    psum[tid] = a;
    __syncthreads();
    if (part == 0) {
        float at = psum[d] + psum[128+d] + psum[256+d] + psum[384+d];
        float vNew = g_v[base+d];
        at += pNew * vNew;
        float invL = 1.0f / L;
        g_ctx[bh*HD + d] = at * invL;
        if (d == 0) { g_m[bh] = M; g_il[bh] = invL; }
        // eviction output for the NEW token (roped k) -> keep slot 515
        size_t doff = ((size_t)bh*KEEP + (KEEP-1))*HD + d;
        out[OFF_K + doff] = kn;
        out[OFF_V + doff] = vNew;
    }
}

// ---------------- 5. merged: importance+chunk-top4 (blocks 0..135) + oproj (136..391) ----
__global__ void __launch_bounds__(256) k_impoproj(
        const float* __restrict__ prev, const float* __restrict__ Wo,
        float* __restrict__ out) {
    int bid = blockIdx.x;
    int tid = threadIdx.x;
    if (bid >= IBLK) {
        // ---- output projection body: attn_out = ctx @ Wo ----
        __shared__ float h_sm[Bb*KC];
        int pid2 = bid - IBLK;             // 0..255
        proj_body256(g_ctx, Wo, out, (pid2 >> 2)*KC, pid2 & 3, h_sm);
        return;
    }
    // ---- importance body ----
    int b     = bid / NCHK;
    int chunk = bid % NCHK;
    int s     = chunk*256 + tid;
    float v = -1e30f;
    if (s < KV) {
        v = 0.f;
        #pragma unroll 4
        for (int h=0; h<Hh; h++) {
            int bh = b*Hh + h;
            v += __expf(g_scores[(size_t)bh*SSTR + s] - g_m[bh]) * g_il[bh];
        }
        v *= (1.0f/32.0f);
        if (s < Ss) v += prev[b*Ss + s];
        g_imp[b*KV + s] = v;
    }
    // block top4 over candidates (s < CAND)
    __shared__ float sv[256];
    __shared__ int   si[256];
    sv[tid] = (s < CAND) ? v : -1e30f;
    si[tid] = (s < CAND) ? s : 0x7FFFFFFF;
    __syncthreads();
    if (tid < 32) {
        float mv[4]; int mi[4];
        #pragma unroll
        for (int r=0;r<4;r++){ mv[r]=-1e30f; mi[r]=0x7FFFFFFF; }
        #pragma unroll
        for (int t=0;t<8;t++) ins4(sv[tid*8+t], si[tid*8+t], mv, mi);
        __syncwarp();
        #pragma unroll
        for (int r=0;r<4;r++){ sv[tid*4+r]=mv[r]; si[tid*4+r]=mi[r]; }
        __syncwarp();
        if (tid == 0) {
            float tv[4]; int ti[4];
            #pragma unroll
            for (int r=0;r<4;r++){ tv[r]=-1e30f; ti[r]=0x7FFFFFFF; }
            for (int e=0;e<128;e++) ins4(sv[e], si[e], tv, ti);
            int o = (b*NCHK + chunk)*4;
            #pragma unroll
            for (int r=0;r<4;r++){ g_bv[o+r]=tv[r]; g_bi[o+r]=ti[r]; }
        }
    }
}

// ---------------- 6. per-batch: merge chunk top4 + imp_kept + top-4 K/V gather ----------
__global__ void k_topk(const float* __restrict__ Kc, const float* __restrict__ Vc,
                       float* __restrict__ out) {
    int b = blockIdx.x;
    int tid = threadIdx.x;                 // 256 threads
    __shared__ int tk[4];
    if (tid == 0) {
        float tv[4]; int ti[4];
        #pragma unroll
        for (int r=0;r<4;r++){ tv[r]=-1e30f; ti[r]=0x7FFFFFFF; }
        for (int e=0;e<NCHK*4;e++) ins4(g_bv[b*NCHK*4+e], g_bi[b*NCHK*4+e], tv, ti);
        #pragma unroll
        for (int a=0;a<4;a++)
            #pragma unroll
            for (int c2=a+1;c2<4;c2++)
                if (ti[c2] < ti[a]) { int t=ti[a]; ti[a]=ti[c2]; ti[c2]=t; }
        #pragma unroll
        for (int r=0;r<4;r++) { g_topk[b*4+r] = ti[r]; tk[r] = ti[r]; }
    }
    __syncthreads();

    for (int j = tid; j < KEEP; j += 256) {
        int idx = (j < 4) ? tk[j] : (CAND + (j-4));
        out[OFF_IMP + b*KEEP + j] = g_imp[b*KV + idx];
    }

    for (int t = tid; t < 4096; t += 256) {
        int h    = t >> 7;
        int r    = (t >> 5) & 3;
        int lane = t & 31;
        int bh   = b*Hh + h;
        int idx  = tk[r];
        size_t soff = ((size_t)bh*Ss + idx)*32 + lane;
        size_t doff = ((size_t)bh*KEEP + r)*32 + lane;
        ((float4*)(out + OFF_K))[doff] = ((const float4*)Kc)[soff];
        ((float4*)(out + OFF_V))[doff] = ((const float4*)Vc)[soff];
    }
}

// ---------------- launch (single stream, 6 nodes) ----------------
extern "C" void kernel_launch(void* const* d_in, const int* in_sizes, int n_in,
                              void* d_out, int out_size) {
    const float* hs   = (const float*)d_in[0];
    const float* pk   = (const float*)d_in[1];
    const float* pv   = (const float*)d_in[2];
    const float* Wq   = (const float*)d_in[3];
    const float* Wk   = (const float*)d_in[4];
    const float* Wv   = (const float*)d_in[5];
    const float* Wo   = (const float*)d_in[6];
    const float* prev = (const float*)d_in[7];
    float* out = (float*)d_out;

    k_zero     <<<(Bb*Dd + 255)/256, 256>>>(out);
    k_projQ    <<<dim3(Dd/512, Dd/KC), 128>>>(hs, Wq);
    k_mega     <<<FBLK + PBLK, 256>>>(pk, pv, hs, Wk, Wv, out);
    k_comb     <<<Bb*Hh, 512>>>(out);
    k_impoproj <<<IBLK + 256, 256>>>(prev, Wo, out);
    k_topk     <<<Bb, 256>>>(pk, pv, out);
}